// round 6
// baseline (speedup 1.0000x reference)
#include <cuda_runtime.h>

// Problem constants
static constexpr int H    = 768;
static constexpr int B    = 64;
static constexpr int S1   = 513;
static constexpr int S    = 512;
static constexpr int NT   = 4;
static constexpr int NP   = 255;   // pair operators (transitions 1..510)
static constexpr int NQ   = 127;   // quad operators (transitions 1..508)

// Output layout (flattened tuple, float32):
// [isqa_pred(64), crf_pred(64*512), isqa_loss(1), crf_loss(1), tags(64*512), IsQA(64)]
static constexpr int OFF_IPRED = 0;
static constexpr int OFF_CPRED = 64;
static constexpr int OFF_ILOSS = 64 + B * S;          // 32832
static constexpr int OFF_CLOSS = OFF_ILOSS + 1;       // 32833
static constexpr int OFF_TAGS  = OFF_CLOSS + 1;       // 32834
static constexpr int OFF_ISQA  = OFF_TAGS + B * S;    // 65602

// Scratch (device globals) — 16B-aligned: accessed via float4
__device__ __align__(16) float g_feats[B * S * NT];   // 512 KB
__device__ float g_logits[B * 2];
__device__ float g_dloss[B];
__device__ float g_iloss[B];

__device__ __forceinline__ int argmax4(float v0, float v1, float v2, float v3,
                                       float& mv) {
    // first-index tie-breaking (jnp.argmax): later wins only on strict >
    float mA = fmaxf(v0, v1); int iA = (v1 > v0) ? 1 : 0;
    float mB = fmaxf(v2, v3); int iB = (v3 > v2) ? 3 : 2;
    mv = fmaxf(mA, mB);
    return (mB > mA) ? iB : iA;
}

// ---------------------------------------------------------------------------
// Kernel 1: emission features + isqa logits.
// Coalesced interleaved loads (lane reads float4 k*32+lane), weights in smem,
// 2 rows per warp iteration (weight-load reuse). Work items:
//   0..16383  : row pairs (b, s=1+2sp, s+1)
//   16384..   : cls rows (s==0) -> fc2 logits
// ---------------------------------------------------------------------------
__global__ void __launch_bounds__(256, 3)
k_feats(const float* __restrict__ emb,
        const float* __restrict__ fc2_W,
        const float* __restrict__ fc2_b,
        const float* __restrict__ crf_W,
        const float* __restrict__ crf_b) {
    __shared__ __align__(16) float sw[NT * H];     // 12 KB, natural layout
    __shared__ __align__(16) float sfc[2 * H];     // 6 KB
    __shared__ float scb[NT];
    __shared__ float sfb[2];

    const int tid = threadIdx.x;
    for (int i = tid; i < NT * H; i += 256) sw[i] = crf_W[i];
    for (int i = tid; i < 2 * H; i += 256) sfc[i] = fc2_W[i];
    if (tid < NT) scb[tid] = crf_b[tid];
    if (tid < 2)  sfb[tid] = fc2_b[tid];
    __syncthreads();

    const int lane = tid & 31;
    const int gw   = (blockIdx.x * blockDim.x + tid) >> 5;
    const int nw   = (gridDim.x * blockDim.x) >> 5;

    for (int it = gw; it < 16384 + B; it += nw) {
        if (it < 16384) {
            const int b  = it >> 8;
            const int sp = it & 255;
            const size_t r0 = (size_t)b * S1 + 1 + 2 * sp;
            const float4* e0 = reinterpret_cast<const float4*>(emb + r0 * H);
            const float4* e1 = reinterpret_cast<const float4*>(emb + (r0 + 1) * H);
            float4 ev0[6], ev1[6];
#pragma unroll
            for (int k = 0; k < 6; k++) {
                ev0[k] = e0[k * 32 + lane];
                ev1[k] = e1[k * 32 + lane];
            }
            float a0[NT] = {0.f, 0.f, 0.f, 0.f};
            float a1[NT] = {0.f, 0.f, 0.f, 0.f};
#pragma unroll
            for (int k = 0; k < 6; k++) {
#pragma unroll
                for (int t = 0; t < NT; t++) {
                    float4 w = reinterpret_cast<const float4*>(sw + t * H)[k * 32 + lane];
                    a0[t] += ev0[k].x * w.x + ev0[k].y * w.y + ev0[k].z * w.z + ev0[k].w * w.w;
                    a1[t] += ev1[k].x * w.x + ev1[k].y * w.y + ev1[k].z * w.z + ev1[k].w * w.w;
                }
            }
#pragma unroll
            for (int off = 16; off; off >>= 1)
#pragma unroll
                for (int t = 0; t < NT; t++) {
                    a0[t] += __shfl_xor_sync(0xFFFFFFFFu, a0[t], off);
                    a1[t] += __shfl_xor_sync(0xFFFFFFFFu, a1[t], off);
                }
            if (lane == 0) {
                float4* dst = reinterpret_cast<float4*>(g_feats) + (b * S + 2 * sp);
                dst[0] = make_float4(a0[0] + scb[0], a0[1] + scb[1],
                                     a0[2] + scb[2], a0[3] + scb[3]);
                dst[1] = make_float4(a1[0] + scb[0], a1[1] + scb[1],
                                     a1[2] + scb[2], a1[3] + scb[3]);
            }
        } else {
            const int b = it - 16384;
            const float4* e = reinterpret_cast<const float4*>(emb + (size_t)b * S1 * H);
            float l0 = 0.f, l1 = 0.f;
#pragma unroll
            for (int k = 0; k < 6; k++) {
                float4 ev = e[k * 32 + lane];
                float4 w0 = reinterpret_cast<const float4*>(sfc)[k * 32 + lane];
                float4 w1 = reinterpret_cast<const float4*>(sfc + H)[k * 32 + lane];
                l0 += ev.x * w0.x + ev.y * w0.y + ev.z * w0.z + ev.w * w0.w;
                l1 += ev.x * w1.x + ev.y * w1.y + ev.z * w1.z + ev.w * w1.w;
            }
#pragma unroll
            for (int off = 16; off; off >>= 1) {
                l0 += __shfl_xor_sync(0xFFFFFFFFu, l0, off);
                l1 += __shfl_xor_sync(0xFFFFFFFFu, l1, off);
            }
            if (lane == 0) {
                g_logits[b * 2 + 0] = l0 + sfb[0];
                g_logits[b * 2 + 1] = l1 + sfb[1];
            }
        }
    }
}

// ---------------------------------------------------------------------------
// Kernel 2: per-batch CRF with 4-step operator folding. 128 threads/block.
// Staging (all threads, parallel): M2 -> M4(normalized), V2(+mid words) ->
// V4(+mid words). Serial (one lane each): forward 127 folds; Viterbi 127
// folds storing per-fold deltas, then backtrace via staged mid words.
// ---------------------------------------------------------------------------
__global__ void k_crf(const int* __restrict__ labels,
                      const int* __restrict__ isqa,
                      const float* __restrict__ trans,
                      float* __restrict__ out) {
    __shared__ __align__(16) float sf[S * NT];     // 8 KB: feats (log)
    __shared__ __align__(16) float sA[NP * 16];    // ~16 KB: M2, then V2
    __shared__ __align__(16) float sM4[NQ * 16];   // ~8 KB (sum-normalized)
    __shared__ __align__(16) float sV4[NQ * 16];   // ~8 KB
    __shared__ __align__(16) float sM2last[16];
    __shared__ __align__(16) float sd4[NQ * 4];    // viterbi fold-input deltas
    __shared__ float slog4[NQ];
    __shared__ float slog2last;
    __shared__ int   skmid4[NQ];
    __shared__ int   sbpmid2[NP];
    __shared__ unsigned char stag[S], spath[S];
    __shared__ float strn[16];
    __shared__ float sZ, sGold;

    const int b   = blockIdx.x;
    const int tid = threadIdx.x;
    const float4* sf4 = reinterpret_cast<const float4*>(sf);

    // ---- P0: stage feats, tags, trans ----
    {
        const float4* fsrc = reinterpret_cast<const float4*>(g_feats + (size_t)b * S * NT);
        float4* f4 = reinterpret_cast<float4*>(sf);
        for (int i = tid; i < S; i += 128) f4[i] = fsrc[i];
        for (int i = tid; i < S; i += 128) {
            int tg = labels[b * S1 + 1 + i];
            stag[i] = (unsigned char)tg;
            out[OFF_TAGS + b * S + i] = (float)tg;
        }
        if (tid < 16) strn[tid] = trans[tid];
    }
    __syncthreads();

    // ---- P1: M2 pair matrices (linear domain) into sA ----
    {
        float E[16];
#pragma unroll
        for (int i = 0; i < 16; i++) E[i] = __expf(strn[i]);
        for (int p = tid; p < NP; p += 128) {
            float4 f1 = sf4[2 * p + 1], f2 = sf4[2 * p + 2];
            float g[4] = {__expf(f1.x), __expf(f1.y), __expf(f1.z), __expf(f1.w)};
            float h[4] = {__expf(f2.x), __expf(f2.y), __expf(f2.z), __expf(f2.w)};
            float* dst = sA + p * 16;
#pragma unroll
            for (int i = 0; i < 4; i++) {
                float eg0 = E[i * 4 + 0] * g[0], eg1 = E[i * 4 + 1] * g[1];
                float eg2 = E[i * 4 + 2] * g[2], eg3 = E[i * 4 + 3] * g[3];
#pragma unroll
                for (int j = 0; j < 4; j++) {
                    dst[i * 4 + j] = ((eg0 * E[0 * 4 + j] + eg1 * E[1 * 4 + j]) +
                                      (eg2 * E[2 * 4 + j] + eg3 * E[3 * 4 + j])) * h[j];
                }
            }
        }
    }
    __syncthreads();

    // ---- P2: M4 = M2*M2, sum-normalized; keep normalized M2[254] ----
    if (tid < NQ) {
        const float* A = sA + (2 * tid) * 16;
        const float* Bm = sA + (2 * tid + 1) * 16;
        float m[16];
        float ssum = 0.f;
#pragma unroll
        for (int i = 0; i < 4; i++)
#pragma unroll
            for (int j = 0; j < 4; j++) {
                float v = (A[i * 4 + 0] * Bm[0 * 4 + j] + A[i * 4 + 1] * Bm[1 * 4 + j]) +
                          (A[i * 4 + 2] * Bm[2 * 4 + j] + A[i * 4 + 3] * Bm[3 * 4 + j]);
                m[i * 4 + j] = v;
                ssum += v;
            }
        float inv = __fdividef(1.0f, ssum);
#pragma unroll
        for (int i = 0; i < 16; i++) sM4[tid * 16 + i] = m[i] * inv;
        slog4[tid] = __logf(ssum);
    } else if (tid == NQ) {
        const float* A = sA + 254 * 16;
        float ssum = 0.f;
#pragma unroll
        for (int i = 0; i < 16; i++) ssum += A[i];
        float inv = __fdividef(1.0f, ssum);
#pragma unroll
        for (int i = 0; i < 16; i++) sM2last[i] = A[i] * inv;
        slog2last = __logf(ssum);
    }
    __syncthreads();

    // ---- P3: V2 (max-plus) overwrites sA; mid-tag words ----
    for (int p = tid; p < NP; p += 128) {
        float4 f1 = sf4[2 * p + 1], f2 = sf4[2 * p + 2];
        float f1a[4] = {f1.x, f1.y, f1.z, f1.w};
        float f2a[4] = {f2.x, f2.y, f2.z, f2.w};
        float* dst = sA + p * 16;
        int word = 0;
#pragma unroll
        for (int i = 0; i < 4; i++) {
            float h0 = strn[i * 4 + 0] + f1a[0], h1 = strn[i * 4 + 1] + f1a[1];
            float h2 = strn[i * 4 + 2] + f1a[2], h3 = strn[i * 4 + 3] + f1a[3];
#pragma unroll
            for (int j = 0; j < 4; j++) {
                float mv;
                int k = argmax4(h0 + strn[0 * 4 + j], h1 + strn[1 * 4 + j],
                                h2 + strn[2 * 4 + j], h3 + strn[3 * 4 + j], mv);
                dst[i * 4 + j] = mv + f2a[j];
                word |= k << (2 * (i * 4 + j));
            }
        }
        sbpmid2[p] = word;
    }
    __syncthreads();

    // ---- P4: V4 = V2 (x) V2 (max-plus), mid-tag words ----
    if (tid < NQ) {
        const float* A = sA + (2 * tid) * 16;
        const float* Bv = sA + (2 * tid + 1) * 16;
        int word = 0;
#pragma unroll
        for (int i = 0; i < 4; i++)
#pragma unroll
            for (int j = 0; j < 4; j++) {
                float mv;
                int k = argmax4(A[i * 4 + 0] + Bv[0 * 4 + j], A[i * 4 + 1] + Bv[1 * 4 + j],
                                A[i * 4 + 2] + Bv[2 * 4 + j], A[i * 4 + 3] + Bv[3 * 4 + j], mv);
                sV4[tid * 16 + i * 4 + j] = mv;
                word |= k << (2 * (i * 4 + j));
            }
        skmid4[tid] = word;
    }
    __syncthreads();

    const int warp = tid >> 5, lane = tid & 31;

    if (warp == 0 && lane == 0) {
        // ---- Forward log-partition: 127 quad folds + pair 254 + step 511 ----
        float E[16];
#pragma unroll
        for (int i = 0; i < 16; i++) E[i] = __expf(strn[i]);
        float4 f0 = sf4[0];
        float a0 = __expf(f0.x) * E[8],  a1 = __expf(f0.y) * E[9];
        float a2 = __expf(f0.z) * E[10], a3 = __expf(f0.w) * E[11];
        float lz = 0.f;
        int q = 0;
#pragma unroll 1
        for (int c = 0; c < 15; c++) {
#pragma unroll
            for (int u = 0; u < 8; u++, q++) {
                const float4* M = reinterpret_cast<const float4*>(sM4 + q * 16);
                float4 r0 = M[0], r1 = M[1], r2 = M[2], r3 = M[3];
                float n0 = (a0 * r0.x + a1 * r1.x) + (a2 * r2.x + a3 * r3.x);
                float n1 = (a0 * r0.y + a1 * r1.y) + (a2 * r2.y + a3 * r3.y);
                float n2 = (a0 * r0.z + a1 * r1.z) + (a2 * r2.z + a3 * r3.z);
                float n3 = (a0 * r0.w + a1 * r1.w) + (a2 * r2.w + a3 * r3.w);
                lz += slog4[q];
                a0 = n0; a1 = n1; a2 = n2; a3 = n3;
            }
            float ssum = (a0 + a1) + (a2 + a3);
            lz += __logf(ssum);
            float inv = __fdividef(1.0f, ssum);
            a0 *= inv; a1 *= inv; a2 *= inv; a3 *= inv;
        }
#pragma unroll
        for (; q < NQ; q++) {
            const float4* M = reinterpret_cast<const float4*>(sM4 + q * 16);
            float4 r0 = M[0], r1 = M[1], r2 = M[2], r3 = M[3];
            float n0 = (a0 * r0.x + a1 * r1.x) + (a2 * r2.x + a3 * r3.x);
            float n1 = (a0 * r0.y + a1 * r1.y) + (a2 * r2.y + a3 * r3.y);
            float n2 = (a0 * r0.z + a1 * r1.z) + (a2 * r2.z + a3 * r3.z);
            float n3 = (a0 * r0.w + a1 * r1.w) + (a2 * r2.w + a3 * r3.w);
            lz += slog4[q];
            a0 = n0; a1 = n1; a2 = n2; a3 = n3;
        }
        {   // pair 254 (transitions 509, 510)
            const float4* M = reinterpret_cast<const float4*>(sM2last);
            float4 r0 = M[0], r1 = M[1], r2 = M[2], r3 = M[3];
            float n0 = (a0 * r0.x + a1 * r1.x) + (a2 * r2.x + a3 * r3.x);
            float n1 = (a0 * r0.y + a1 * r1.y) + (a2 * r2.y + a3 * r3.y);
            float n2 = (a0 * r0.z + a1 * r1.z) + (a2 * r2.z + a3 * r3.z);
            float n3 = (a0 * r0.w + a1 * r1.w) + (a2 * r2.w + a3 * r3.w);
            lz += slog2last;
            a0 = n0; a1 = n1; a2 = n2; a3 = n3;
        }
        {   // single transition 511 + stop
            float4 f = sf4[511];
            float t0 = ((a0 * E[0] + a1 * E[4]) + (a2 * E[8]  + a3 * E[12])) * __expf(f.x);
            float t1 = ((a0 * E[1] + a1 * E[5]) + (a2 * E[9]  + a3 * E[13])) * __expf(f.y);
            float t2 = ((a0 * E[2] + a1 * E[6]) + (a2 * E[10] + a3 * E[14])) * __expf(f.z);
            float t3 = ((a0 * E[3] + a1 * E[7]) + (a2 * E[11] + a3 * E[15])) * __expf(f.w);
            sZ = lz + __logf((t0 * E[3] + t1 * E[7]) + (t2 * E[11] + t3 * E[15]));
        }
    } else if (warp == 1 && lane == 0) {
        // ---- Viterbi: 127 quad folds (store input deltas) + leftovers ----
        float4 f0 = sf4[0];
        float d0 = f0.x + strn[8],  d1 = f0.y + strn[9];
        float d2 = f0.z + strn[10], d3 = f0.w + strn[11];
#pragma unroll 2
        for (int q = 0; q < NQ; q++) {
            reinterpret_cast<float4*>(sd4)[q] = make_float4(d0, d1, d2, d3);
            const float4* V = reinterpret_cast<const float4*>(sV4 + q * 16);
            float4 r0 = V[0], r1 = V[1], r2 = V[2], r3 = V[3];
            float n0 = fmaxf(fmaxf(d0 + r0.x, d1 + r1.x), fmaxf(d2 + r2.x, d3 + r3.x));
            float n1 = fmaxf(fmaxf(d0 + r0.y, d1 + r1.y), fmaxf(d2 + r2.y, d3 + r3.y));
            float n2 = fmaxf(fmaxf(d0 + r0.z, d1 + r1.z), fmaxf(d2 + r2.z, d3 + r3.z));
            float n3 = fmaxf(fmaxf(d0 + r0.w, d1 + r1.w), fmaxf(d2 + r2.w, d3 + r3.w));
            d0 = n0; d1 = n1; d2 = n2; d3 = n3;
        }
        // d508
        float e0 = d0, e1 = d1, e2 = d2, e3 = d3;
        // pair 254 -> d510
        const float* Vl = sA + 254 * 16;
        float g0 = fmaxf(fmaxf(e0 + Vl[0], e1 + Vl[4]), fmaxf(e2 + Vl[8],  e3 + Vl[12]));
        float g1 = fmaxf(fmaxf(e0 + Vl[1], e1 + Vl[5]), fmaxf(e2 + Vl[9],  e3 + Vl[13]));
        float g2 = fmaxf(fmaxf(e0 + Vl[2], e1 + Vl[6]), fmaxf(e2 + Vl[10], e3 + Vl[14]));
        float g3 = fmaxf(fmaxf(e0 + Vl[3], e1 + Vl[7]), fmaxf(e2 + Vl[11], e3 + Vl[15]));
        // single 511 -> d511
        float4 f511 = sf4[511];
        float mv;
        float h0 = fmaxf(fmaxf(g0 + strn[0], g1 + strn[4]), fmaxf(g2 + strn[8],  g3 + strn[12])) + f511.x;
        float h1 = fmaxf(fmaxf(g0 + strn[1], g1 + strn[5]), fmaxf(g2 + strn[9],  g3 + strn[13])) + f511.y;
        float h2 = fmaxf(fmaxf(g0 + strn[2], g1 + strn[6]), fmaxf(g2 + strn[10], g3 + strn[14])) + f511.z;
        float h3 = fmaxf(fmaxf(g0 + strn[3], g1 + strn[7]), fmaxf(g2 + strn[11], g3 + strn[15])) + f511.w;
        // stop -> last tag
        int lt = argmax4(h0 + strn[3], h1 + strn[7], h2 + strn[11], h3 + strn[15], mv);
        spath[511] = (unsigned char)lt;
        // pos 510
        int t510 = argmax4(g0 + strn[0 * 4 + lt], g1 + strn[1 * 4 + lt],
                           g2 + strn[2 * 4 + lt], g3 + strn[3 * 4 + lt], mv);
        spath[510] = (unsigned char)t510;
        // pair 254: pos 508, 509
        int j = t510;
        int i508 = argmax4(e0 + Vl[0 * 4 + j], e1 + Vl[1 * 4 + j],
                           e2 + Vl[2 * 4 + j], e3 + Vl[3 * 4 + j], mv);
        int mid = (sbpmid2[254] >> (2 * ((i508 << 2) | j))) & 3;
        spath[509] = (unsigned char)mid;
        spath[508] = (unsigned char)i508;
        j = i508;
        // quads
#pragma unroll 2
        for (int q = NQ - 1; q >= 0; q--) {
            float4 dv = reinterpret_cast<const float4*>(sd4)[q];
            const float* V = sV4 + q * 16 + j;
            int i = argmax4(dv.x + V[0], dv.y + V[4], dv.z + V[8], dv.w + V[12], mv);
            int k2 = (skmid4[q]       >> (2 * ((i  << 2) | j)))  & 3;
            int m1 = (sbpmid2[2 * q]  >> (2 * ((i  << 2) | k2))) & 3;
            int m3 = (sbpmid2[2 * q + 1] >> (2 * ((k2 << 2) | j))) & 3;
            spath[4 * q]     = (unsigned char)i;
            spath[4 * q + 1] = (unsigned char)m1;
            spath[4 * q + 2] = (unsigned char)k2;
            spath[4 * q + 3] = (unsigned char)m3;
            j = i;
        }
    } else if (warp == 2) {
        // ---- Gold score + isqa ----
        float em = 0.f, tr = 0.f;
        for (int s = lane; s < S; s += 32)     em += sf[s * NT + stag[s]];
        for (int s = lane; s < S - 1; s += 32) tr += strn[stag[s] * NT + stag[s + 1]];
        float v = em + tr;
#pragma unroll
        for (int off = 16; off; off >>= 1) v += __shfl_xor_sync(0xFFFFFFFFu, v, off);
        if (lane == 0) {
            sGold = v + strn[8 + stag[0]] + strn[stag[S - 1] * 4 + 3];
            float l0 = g_logits[b * 2], l1 = g_logits[b * 2 + 1];
            float mm  = fmaxf(l0, l1);
            float lse = mm + __logf(__expf(l0 - mm) + __expf(l1 - mm));
            int y = isqa[b];
            g_iloss[b] = -((y ? l1 : l0) - lse);
            out[OFF_IPRED + b] = (l1 > l0) ? 1.0f : 0.0f;
            out[OFF_ISQA + b] = (float)y;
        }
    }
    __syncthreads();
    if (tid == 0) g_dloss[b] = sZ - sGold;
    for (int i = tid; i < S; i += 128)
        out[OFF_CPRED + b * S + i] = (float)spath[i];
}

// ---------------------------------------------------------------------------
// Kernel 3: reduce per-batch losses to the two scalar outputs
// ---------------------------------------------------------------------------
__global__ void k_final(float* __restrict__ out) {
    const int tid = threadIdx.x;   // 64 threads
    float d  = g_dloss[tid];
    float il = g_iloss[tid];
#pragma unroll
    for (int off = 16; off; off >>= 1) {
        d  += __shfl_xor_sync(0xFFFFFFFFu, d, off);
        il += __shfl_xor_sync(0xFFFFFFFFu, il, off);
    }
    __shared__ float sd2[2], si2[2];
    if ((tid & 31) == 0) { sd2[tid >> 5] = d; si2[tid >> 5] = il; }
    __syncthreads();
    if (tid == 0) {
        out[OFF_CLOSS] = (sd2[0] + sd2[1]) * (1.0f / 64.0f);
        out[OFF_ILOSS] = (si2[0] + si2[1]) * (1.0f / 64.0f);
    }
}

// ---------------------------------------------------------------------------
extern "C" void kernel_launch(void* const* d_in, const int* in_sizes, int n_in,
                              void* d_out, int out_size) {
    const float* emb    = (const float*)d_in[0];
    const int*   labels = (const int*)d_in[1];
    const int*   isqa   = (const int*)d_in[2];
    const float* fc2_W  = (const float*)d_in[3];
    const float* fc2_b  = (const float*)d_in[4];
    const float* crf_W  = (const float*)d_in[5];
    const float* crf_b  = (const float*)d_in[6];
    const float* trans  = (const float*)d_in[7];
    float* out = (float*)d_out;

    k_feats<<<2056, 256>>>(emb, fc2_W, fc2_b, crf_W, crf_b);
    k_crf<<<B, 128>>>(labels, isqa, trans, out);
    k_final<<<1, 64>>>(out);
}

// round 7
// speedup vs baseline: 1.4033x; 1.4033x over previous
#include <cuda_runtime.h>

// Problem constants
static constexpr int H    = 768;
static constexpr int B    = 64;
static constexpr int S1   = 513;
static constexpr int S    = 512;
static constexpr int NT   = 4;
static constexpr int NP   = 255;   // pair operators (steps 1..510)
static constexpr int NQ   = 127;   // quad operators (steps 1..508)

// Output layout (flattened tuple, float32):
// [isqa_pred(64), crf_pred(64*512), isqa_loss(1), crf_loss(1), tags(64*512), IsQA(64)]
static constexpr int OFF_IPRED = 0;
static constexpr int OFF_CPRED = 64;
static constexpr int OFF_ILOSS = 64 + B * S;          // 32832
static constexpr int OFF_CLOSS = OFF_ILOSS + 1;       // 32833
static constexpr int OFF_TAGS  = OFF_CLOSS + 1;       // 32834
static constexpr int OFF_ISQA  = OFF_TAGS + B * S;    // 65602

__device__ __align__(16) float g_feats[B * S * NT];   // 512 KB
__device__ float g_logits[B * 2];
__device__ float g_dloss[B];
__device__ float g_iloss[B];

__device__ __forceinline__ int argmax4(float v0, float v1, float v2, float v3,
                                       float& mv) {
    // first-index tie-breaking (jnp.argmax): later wins only on strict >
    float mA = fmaxf(v0, v1); int iA = (v1 > v0) ? 1 : 0;
    float mB = fmaxf(v2, v3); int iB = (v3 > v2) ? 3 : 2;
    mv = fmaxf(mA, mB);
    return (mB > mA) ? iB : iA;
}

// C = A * B (4x4, row-major; row vector acts from the left)
__device__ __forceinline__ void mm4(const float* A, const float* Bm, float* C) {
#pragma unroll
    for (int i = 0; i < 4; i++)
#pragma unroll
        for (int j = 0; j < 4; j++)
            C[i * 4 + j] = (A[i * 4 + 0] * Bm[0 * 4 + j] + A[i * 4 + 1] * Bm[1 * 4 + j]) +
                           (A[i * 4 + 2] * Bm[2 * 4 + j] + A[i * 4 + 3] * Bm[3 * 4 + j]);
}

// C = A (max-plus) B
__device__ __forceinline__ void mp4(const float* A, const float* Bm, float* C) {
#pragma unroll
    for (int i = 0; i < 4; i++)
#pragma unroll
        for (int j = 0; j < 4; j++)
            C[i * 4 + j] = fmaxf(fmaxf(A[i * 4 + 0] + Bm[0 * 4 + j],
                                       A[i * 4 + 1] + Bm[1 * 4 + j]),
                                 fmaxf(A[i * 4 + 2] + Bm[2 * 4 + j],
                                       A[i * 4 + 3] + Bm[3 * 4 + j]));
}

// ---------------------------------------------------------------------------
// Kernel 1: emission features + isqa logits.
// 1 row per warp-iteration, interleaved coalesced float4 loads, weights in
// smem, ~7 iterations per warp (pipelined), 4 blocks/SM.
// ---------------------------------------------------------------------------
__global__ void __launch_bounds__(256, 4)
k_feats(const float* __restrict__ emb,
        const float* __restrict__ fc2_W,
        const float* __restrict__ fc2_b,
        const float* __restrict__ crf_W,
        const float* __restrict__ crf_b) {
    __shared__ __align__(16) float sw[NT * H];     // 12 KB
    __shared__ __align__(16) float sfc[2 * H];     // 6 KB
    __shared__ float scb[NT];
    __shared__ float sfb[2];

    const int tid = threadIdx.x;
    for (int i = tid; i < NT * H; i += 256) sw[i] = crf_W[i];
    for (int i = tid; i < 2 * H; i += 256) sfc[i] = fc2_W[i];
    if (tid < NT) scb[tid] = crf_b[tid];
    if (tid < 2)  sfb[tid] = fc2_b[tid];
    __syncthreads();

    const int lane = tid & 31;
    const int gw   = (blockIdx.x * blockDim.x + tid) >> 5;
    const int nw   = (gridDim.x * blockDim.x) >> 5;

    for (int r = gw; r < B * S1; r += nw) {
        const int b = r / S1;
        const int s = r - b * S1;
        const float4* e = reinterpret_cast<const float4*>(emb + (size_t)r * H);
        float4 ev[6];
#pragma unroll
        for (int k = 0; k < 6; k++) ev[k] = e[k * 32 + lane];

        if (s == 0) {
            float l0 = 0.f, l1 = 0.f;
#pragma unroll
            for (int k = 0; k < 6; k++) {
                float4 w0 = reinterpret_cast<const float4*>(sfc)[k * 32 + lane];
                float4 w1 = reinterpret_cast<const float4*>(sfc + H)[k * 32 + lane];
                l0 += ev[k].x * w0.x + ev[k].y * w0.y + ev[k].z * w0.z + ev[k].w * w0.w;
                l1 += ev[k].x * w1.x + ev[k].y * w1.y + ev[k].z * w1.z + ev[k].w * w1.w;
            }
#pragma unroll
            for (int off = 16; off; off >>= 1) {
                l0 += __shfl_xor_sync(0xFFFFFFFFu, l0, off);
                l1 += __shfl_xor_sync(0xFFFFFFFFu, l1, off);
            }
            if (lane == 0) {
                g_logits[b * 2 + 0] = l0 + sfb[0];
                g_logits[b * 2 + 1] = l1 + sfb[1];
            }
        } else {
            float acc[NT] = {0.f, 0.f, 0.f, 0.f};
#pragma unroll
            for (int t = 0; t < NT; t++) {
#pragma unroll
                for (int k = 0; k < 6; k++) {
                    float4 w = reinterpret_cast<const float4*>(sw + t * H)[k * 32 + lane];
                    acc[t] += ev[k].x * w.x + ev[k].y * w.y +
                              ev[k].z * w.z + ev[k].w * w.w;
                }
            }
#pragma unroll
            for (int off = 16; off; off >>= 1)
#pragma unroll
                for (int t = 0; t < NT; t++)
                    acc[t] += __shfl_xor_sync(0xFFFFFFFFu, acc[t], off);
            if (lane == 0) {
                reinterpret_cast<float4*>(g_feats)[b * S + (s - 1)] =
                    make_float4(acc[0] + scb[0], acc[1] + scb[1],
                                acc[2] + scb[2], acc[3] + scb[3]);
            }
        }
    }
}

// ---------------------------------------------------------------------------
// Kernel 2: per-batch CRF, fully parallel except a 127-step bit-chase.
//  Forward Z : binary TREE reduction over 255 M2 matrices (normalized+logs)
//  Viterbi   : Hillis-Steele inclusive max-plus SCAN over 127 V4 operators,
//              parallel per-quad backtrace records, serial record chase.
// ---------------------------------------------------------------------------
__global__ void k_crf(const int* __restrict__ labels,
                      const int* __restrict__ isqa,
                      const float* __restrict__ trans,
                      float* __restrict__ out) {
    __shared__ __align__(16) float sf[S * NT];     // 8 KB feats (log)
    __shared__ float sA[NP * 16];                  // 16 KB: M2, then V2
    __shared__ float sV4[NQ * 16];                 // 8 KB
    __shared__ float sPa[128 * 16];                // 8 KB: tree / scan buffer
    __shared__ float slogs[128];
    __shared__ float strn[16], sE[16];
    __shared__ int   sbpmid2[NP];
    __shared__ int   skmid4[NQ];
    __shared__ unsigned int srec[NQ];
    __shared__ unsigned char stag[S], spath[S];
    __shared__ float sZ;

    const int b   = blockIdx.x;
    const int tid = threadIdx.x;
    const float4* sf4 = reinterpret_cast<const float4*>(sf);

    // ---- P0: stage ----
    {
        const float4* fsrc = reinterpret_cast<const float4*>(g_feats + (size_t)b * S * NT);
        float4* f4 = reinterpret_cast<float4*>(sf);
        for (int i = tid; i < S; i += 128) f4[i] = fsrc[i];
        for (int i = tid; i < S; i += 128) {
            int tg = labels[b * S1 + 1 + i];
            stag[i] = (unsigned char)tg;
            out[OFF_TAGS + b * S + i] = (float)tg;
        }
        if (tid < 16) { float t = trans[tid]; strn[tid] = t; sE[tid] = __expf(t); }
    }
    __syncthreads();

    // ---- P1: M2 pair matrices (linear domain) ----
    for (int p = tid; p < NP; p += 128) {
        float4 f1 = sf4[2 * p + 1], f2 = sf4[2 * p + 2];
        float g[4] = {__expf(f1.x), __expf(f1.y), __expf(f1.z), __expf(f1.w)};
        float h[4] = {__expf(f2.x), __expf(f2.y), __expf(f2.z), __expf(f2.w)};
        float* dst = sA + p * 16;
#pragma unroll
        for (int i = 0; i < 4; i++) {
            float eg0 = sE[i * 4 + 0] * g[0], eg1 = sE[i * 4 + 1] * g[1];
            float eg2 = sE[i * 4 + 2] * g[2], eg3 = sE[i * 4 + 3] * g[3];
#pragma unroll
            for (int j = 0; j < 4; j++)
                dst[i * 4 + j] = ((eg0 * sE[0 * 4 + j] + eg1 * sE[1 * 4 + j]) +
                                  (eg2 * sE[2 * 4 + j] + eg3 * sE[3 * 4 + j])) * h[j];
        }
    }
    __syncthreads();

    // ---- P2: forward Z via tree reduction ----
    {   // level 1: 255 -> 128 (last node = passthrough of M2[254])
        float C[16];
        if (tid < 127) mm4(sA + 32 * tid, sA + 32 * tid + 16, C);
        else { const float* M = sA + 254 * 16;
#pragma unroll
               for (int i = 0; i < 16; i++) C[i] = M[i]; }
        float ssum = 0.f;
#pragma unroll
        for (int i = 0; i < 16; i++) ssum += C[i];
        float inv = __fdividef(1.0f, ssum);
#pragma unroll
        for (int i = 0; i < 16; i++) sPa[tid * 16 + i] = C[i] * inv;
        slogs[tid] = __logf(ssum);
    }
    __syncthreads();
#pragma unroll
    for (int n = 64; n >= 1; n >>= 1) {
        float C[16], lg = 0.f;
        if (tid < n) { mm4(sPa + 32 * tid, sPa + 32 * tid + 16, C);
                       lg = slogs[2 * tid] + slogs[2 * tid + 1]; }
        __syncthreads();
        if (tid < n) {
            float ssum = 0.f;
#pragma unroll
            for (int i = 0; i < 16; i++) ssum += C[i];
            float inv = __fdividef(1.0f, ssum);
#pragma unroll
            for (int i = 0; i < 16; i++) sPa[tid * 16 + i] = C[i] * inv;
            slogs[tid] = lg + __logf(ssum);
        }
        __syncthreads();
    }
    if (tid == 0) {   // Z epilogue: alpha0 . Mtot, then step 511 + stop
        float4 f0 = sf4[0];
        float a[4] = {__expf(f0.x) * sE[8],  __expf(f0.y) * sE[9],
                      __expf(f0.z) * sE[10], __expf(f0.w) * sE[11]};
        float t[4];
#pragma unroll
        for (int j = 0; j < 4; j++)
            t[j] = (a[0] * sPa[0 * 4 + j] + a[1] * sPa[1 * 4 + j]) +
                   (a[2] * sPa[2 * 4 + j] + a[3] * sPa[3 * 4 + j]);
        float4 f511 = sf4[511];
        float ef[4] = {__expf(f511.x), __expf(f511.y), __expf(f511.z), __expf(f511.w)};
        float u[4];
#pragma unroll
        for (int j = 0; j < 4; j++)
            u[j] = ((t[0] * sE[0 * 4 + j] + t[1] * sE[1 * 4 + j]) +
                    (t[2] * sE[2 * 4 + j] + t[3] * sE[3 * 4 + j])) * ef[j];
        sZ = slogs[0] + __logf((u[0] * sE[3] + u[1] * sE[7]) +
                               (u[2] * sE[11] + u[3] * sE[15]));
    }
    __syncthreads();

    // ---- P3: V2 (max-plus) overwrites sA; mid-tag words ----
    for (int p = tid; p < NP; p += 128) {
        float4 f1 = sf4[2 * p + 1], f2 = sf4[2 * p + 2];
        float f1a[4] = {f1.x, f1.y, f1.z, f1.w};
        float f2a[4] = {f2.x, f2.y, f2.z, f2.w};
        float* dst = sA + p * 16;
        int word = 0;
#pragma unroll
        for (int i = 0; i < 4; i++) {
            float h0 = strn[i * 4 + 0] + f1a[0], h1 = strn[i * 4 + 1] + f1a[1];
            float h2 = strn[i * 4 + 2] + f1a[2], h3 = strn[i * 4 + 3] + f1a[3];
#pragma unroll
            for (int j = 0; j < 4; j++) {
                float mv;
                int k = argmax4(h0 + strn[0 * 4 + j], h1 + strn[1 * 4 + j],
                                h2 + strn[2 * 4 + j], h3 + strn[3 * 4 + j], mv);
                dst[i * 4 + j] = mv + f2a[j];
                word |= k << (2 * (i * 4 + j));
            }
        }
        sbpmid2[p] = word;
    }
    __syncthreads();

    // ---- P4: V4 = V2 o V2 into sV4 AND sPa (scan init); mid words ----
    if (tid < NQ) {
        const float* A = sA + (2 * tid) * 16;
        const float* Bv = sA + (2 * tid + 1) * 16;
        int word = 0;
#pragma unroll
        for (int i = 0; i < 4; i++)
#pragma unroll
            for (int j = 0; j < 4; j++) {
                float mv;
                int k = argmax4(A[i * 4 + 0] + Bv[0 * 4 + j], A[i * 4 + 1] + Bv[1 * 4 + j],
                                A[i * 4 + 2] + Bv[2 * 4 + j], A[i * 4 + 3] + Bv[3 * 4 + j], mv);
                sV4[tid * 16 + i * 4 + j] = mv;
                sPa[tid * 16 + i * 4 + j] = mv;
                word |= k << (2 * (i * 4 + j));
            }
        skmid4[tid] = word;
    }
    __syncthreads();

    // ---- P5: inclusive max-plus scan of V4 prefixes (Hillis-Steele) ----
#pragma unroll
    for (int d = 1; d < 128; d <<= 1) {
        float C[16];
        const bool act = (tid < NQ) && (tid >= d);
        if (act) mp4(sPa + (tid - d) * 16, sPa + tid * 16, C);
        __syncthreads();
        if (act) {
#pragma unroll
            for (int i = 0; i < 16; i++) sPa[tid * 16 + i] = C[i];
        }
        __syncthreads();
    }

    // ---- P6: per-quad backtrace records (parallel) ----
    if (tid < NQ) {
        const int q = tid;
        float de[4];
        float4 f0 = sf4[0];
        float d0v[4] = {f0.x + strn[8], f0.y + strn[9], f0.z + strn[10], f0.w + strn[11]};
        if (q == 0) {
#pragma unroll
            for (int i = 0; i < 4; i++) de[i] = d0v[i];
        } else {
            const float* P = sPa + (q - 1) * 16;
#pragma unroll
            for (int j = 0; j < 4; j++) {
                float mv;
                argmax4(d0v[0] + P[0 * 4 + j], d0v[1] + P[1 * 4 + j],
                        d0v[2] + P[2 * 4 + j], d0v[3] + P[3 * 4 + j], mv);
                de[j] = mv;
            }
        }
        const float* V = sV4 + q * 16;
        const int w4 = skmid4[q], w2a = sbpmid2[2 * q], w2b = sbpmid2[2 * q + 1];
        unsigned int rec = 0;
#pragma unroll
        for (int j = 0; j < 4; j++) {
            float mv;
            int i = argmax4(de[0] + V[0 * 4 + j], de[1] + V[1 * 4 + j],
                            de[2] + V[2 * 4 + j], de[3] + V[3 * 4 + j], mv);
            int k2 = (w4  >> (2 * ((i  << 2) | j)))  & 3;
            int m1 = (w2a >> (2 * ((i  << 2) | k2))) & 3;
            int m3 = (w2b >> (2 * ((k2 << 2) | j)))  & 3;
            rec |= (unsigned int)(i | (m1 << 2) | (k2 << 4) | (m3 << 6)) << (8 * j);
        }
        srec[q] = rec;
    }
    __syncthreads();

    // ---- P7: viterbi epilogue + serial record chase (tid 0) ----
    if (tid == 0) {
        float4 f0 = sf4[0];
        float d0v[4] = {f0.x + strn[8], f0.y + strn[9], f0.z + strn[10], f0.w + strn[11]};
        // delta at position 508 = delta0 (max-plus) P[126]
        const float* P = sPa + 126 * 16;
        float e[4];
#pragma unroll
        for (int j = 0; j < 4; j++) {
            float mv;
            argmax4(d0v[0] + P[0 * 4 + j], d0v[1] + P[1 * 4 + j],
                    d0v[2] + P[2 * 4 + j], d0v[3] + P[3 * 4 + j], mv);
            e[j] = mv;
        }
        // pair 254 (steps 509,510) -> delta510
        const float* Vl = sA + 254 * 16;
        float g0 = fmaxf(fmaxf(e[0] + Vl[0], e[1] + Vl[4]), fmaxf(e[2] + Vl[8],  e[3] + Vl[12]));
        float g1 = fmaxf(fmaxf(e[0] + Vl[1], e[1] + Vl[5]), fmaxf(e[2] + Vl[9],  e[3] + Vl[13]));
        float g2 = fmaxf(fmaxf(e[0] + Vl[2], e[1] + Vl[6]), fmaxf(e[2] + Vl[10], e[3] + Vl[14]));
        float g3 = fmaxf(fmaxf(e[0] + Vl[3], e[1] + Vl[7]), fmaxf(e[2] + Vl[11], e[3] + Vl[15]));
        // step 511
        float4 f511 = sf4[511];
        float h0 = fmaxf(fmaxf(g0 + strn[0], g1 + strn[4]), fmaxf(g2 + strn[8],  g3 + strn[12])) + f511.x;
        float h1 = fmaxf(fmaxf(g0 + strn[1], g1 + strn[5]), fmaxf(g2 + strn[9],  g3 + strn[13])) + f511.y;
        float h2 = fmaxf(fmaxf(g0 + strn[2], g1 + strn[6]), fmaxf(g2 + strn[10], g3 + strn[14])) + f511.z;
        float h3 = fmaxf(fmaxf(g0 + strn[3], g1 + strn[7]), fmaxf(g2 + strn[11], g3 + strn[15])) + f511.w;
        float mv;
        int lt = argmax4(h0 + strn[3], h1 + strn[7], h2 + strn[11], h3 + strn[15], mv);
        spath[511] = (unsigned char)lt;
        int t510 = argmax4(g0 + strn[0 * 4 + lt], g1 + strn[1 * 4 + lt],
                           g2 + strn[2 * 4 + lt], g3 + strn[3 * 4 + lt], mv);
        spath[510] = (unsigned char)t510;
        int j = t510;
        int i508 = argmax4(e[0] + Vl[0 * 4 + j], e[1] + Vl[1 * 4 + j],
                           e[2] + Vl[2 * 4 + j], e[3] + Vl[3 * 4 + j], mv);
        int mid = (sbpmid2[254] >> (2 * ((i508 << 2) | j))) & 3;
        spath[509] = (unsigned char)mid;
        spath[508] = (unsigned char)i508;
        j = i508;
        // record chase: 127 dependent steps of shift/and
        unsigned int* path32 = reinterpret_cast<unsigned int*>(spath);
#pragma unroll 4
        for (int q = NQ - 1; q >= 0; q--) {
            unsigned int w = srec[q];
            unsigned int r = (w >> (8 * j)) & 255u;
            path32[q] = (r & 3u) | (((r >> 2) & 3u) << 8) |
                        (((r >> 4) & 3u) << 16) | (((r >> 6) & 3u) << 24);
            j = (int)(r & 3u);
        }
    }
    __syncthreads();

    // ---- P8: gold score (warp 0), isqa (tid 32), path writeback (all) ----
    const int warp = tid >> 5, lane = tid & 31;
    if (warp == 0) {
        float em = 0.f, tr = 0.f;
        for (int s = lane; s < S; s += 32)     em += sf[s * NT + stag[s]];
        for (int s = lane; s < S - 1; s += 32) tr += strn[stag[s] * NT + stag[s + 1]];
        float v = em + tr;
#pragma unroll
        for (int off = 16; off; off >>= 1) v += __shfl_xor_sync(0xFFFFFFFFu, v, off);
        if (lane == 0) {
            float gold = v + strn[8 + stag[0]] + strn[stag[S - 1] * 4 + 3];
            g_dloss[b] = sZ - gold;
        }
    } else if (tid == 32) {
        float l0 = g_logits[b * 2], l1 = g_logits[b * 2 + 1];
        float mm  = fmaxf(l0, l1);
        float lse = mm + __logf(__expf(l0 - mm) + __expf(l1 - mm));
        int y = isqa[b];
        g_iloss[b] = -((y ? l1 : l0) - lse);
        out[OFF_IPRED + b] = (l1 > l0) ? 1.0f : 0.0f;
        out[OFF_ISQA + b] = (float)y;
    }
    for (int i = tid; i < S; i += 128)
        out[OFF_CPRED + b * S + i] = (float)spath[i];
}

// ---------------------------------------------------------------------------
// Kernel 3: reduce per-batch losses
// ---------------------------------------------------------------------------
__global__ void k_final(float* __restrict__ out) {
    const int tid = threadIdx.x;   // 64 threads
    float d  = g_dloss[tid];
    float il = g_iloss[tid];
#pragma unroll
    for (int off = 16; off; off >>= 1) {
        d  += __shfl_xor_sync(0xFFFFFFFFu, d, off);
        il += __shfl_xor_sync(0xFFFFFFFFu, il, off);
    }
    __shared__ float sd2[2], si2[2];
    if ((tid & 31) == 0) { sd2[tid >> 5] = d; si2[tid >> 5] = il; }
    __syncthreads();
    if (tid == 0) {
        out[OFF_CLOSS] = (sd2[0] + sd2[1]) * (1.0f / 64.0f);
        out[OFF_ILOSS] = (si2[0] + si2[1]) * (1.0f / 64.0f);
    }
}

// ---------------------------------------------------------------------------
extern "C" void kernel_launch(void* const* d_in, const int* in_sizes, int n_in,
                              void* d_out, int out_size) {
    const float* emb    = (const float*)d_in[0];
    const int*   labels = (const int*)d_in[1];
    const int*   isqa   = (const int*)d_in[2];
    const float* fc2_W  = (const float*)d_in[3];
    const float* fc2_b  = (const float*)d_in[4];
    const float* crf_W  = (const float*)d_in[5];
    const float* crf_b  = (const float*)d_in[6];
    const float* trans  = (const float*)d_in[7];
    float* out = (float*)d_out;

    k_feats<<<592, 256>>>(emb, fc2_W, fc2_b, crf_W, crf_b);
    k_crf<<<B, 128>>>(labels, isqa, trans, out);
    k_final<<<1, 64>>>(out);
}

// round 8
// speedup vs baseline: 2.1495x; 1.5317x over previous
#include <cuda_runtime.h>

// Problem constants
static constexpr int H    = 768;
static constexpr int B    = 64;
static constexpr int S1   = 513;
static constexpr int S    = 512;
static constexpr int NT   = 4;
static constexpr int NP   = 255;   // pair operators (steps 1..510)
static constexpr int NQ   = 127;   // quad operators (steps 1..508)
static constexpr int PSTR = 256;   // SoA stride for pair-level arrays
static constexpr int QSTR = 128;   // SoA stride for quad-level arrays

// Output layout (flattened tuple, float32):
// [isqa_pred(64), crf_pred(64*512), isqa_loss(1), crf_loss(1), tags(64*512), IsQA(64)]
static constexpr int OFF_IPRED = 0;
static constexpr int OFF_CPRED = 64;
static constexpr int OFF_ILOSS = 64 + B * S;          // 32832
static constexpr int OFF_CLOSS = OFF_ILOSS + 1;       // 32833
static constexpr int OFF_TAGS  = OFF_CLOSS + 1;       // 32834
static constexpr int OFF_ISQA  = OFF_TAGS + B * S;    // 65602

__device__ __align__(16) float g_feats[B * S * NT];   // 512 KB
__device__ float g_logits[B * 2];
__device__ float g_dloss[B];
__device__ float g_iloss[B];

__device__ __forceinline__ int argmax4(float v0, float v1, float v2, float v3,
                                       float& mv) {
    // first-index tie-breaking (jnp.argmax): later wins only on strict >
    float mA = fmaxf(v0, v1); int iA = (v1 > v0) ? 1 : 0;
    float mB = fmaxf(v2, v3); int iB = (v3 > v2) ? 3 : 2;
    mv = fmaxf(mA, mB);
    return (mB > mA) ? iB : iA;
}

// C = A * B (4x4, row-major register arrays)
__device__ __forceinline__ void mm4(const float* A, const float* Bm, float* C) {
#pragma unroll
    for (int i = 0; i < 4; i++)
#pragma unroll
        for (int j = 0; j < 4; j++)
            C[i * 4 + j] = (A[i * 4 + 0] * Bm[0 * 4 + j] + A[i * 4 + 1] * Bm[1 * 4 + j]) +
                           (A[i * 4 + 2] * Bm[2 * 4 + j] + A[i * 4 + 3] * Bm[3 * 4 + j]);
}

// C = A (max-plus) B
__device__ __forceinline__ void mp4(const float* A, const float* Bm, float* C) {
#pragma unroll
    for (int i = 0; i < 4; i++)
#pragma unroll
        for (int j = 0; j < 4; j++)
            C[i * 4 + j] = fmaxf(fmaxf(A[i * 4 + 0] + Bm[0 * 4 + j],
                                       A[i * 4 + 1] + Bm[1 * 4 + j]),
                                 fmaxf(A[i * 4 + 2] + Bm[2 * 4 + j],
                                       A[i * 4 + 3] + Bm[3 * 4 + j]));
}

// ---------------------------------------------------------------------------
// Kernel 1: emission features + isqa logits.
// 2 rows per warp-iteration (halves weight-LDS traffic, doubles MLP),
// interleaved coalesced float4 loads, pipelined grid-stride (>=4 iters/warp).
// Items 0..16383: row pairs; 16384..16447: cls rows.
// ---------------------------------------------------------------------------
__global__ void __launch_bounds__(256, 3)
k_feats(const float* __restrict__ emb,
        const float* __restrict__ fc2_W,
        const float* __restrict__ fc2_b,
        const float* __restrict__ crf_W,
        const float* __restrict__ crf_b) {
    __shared__ __align__(16) float sw[NT * H];     // 12 KB
    __shared__ __align__(16) float sfc[2 * H];     // 6 KB
    __shared__ float scb[NT];
    __shared__ float sfb[2];

    const int tid = threadIdx.x;
    for (int i = tid; i < NT * H; i += 256) sw[i] = crf_W[i];
    for (int i = tid; i < 2 * H; i += 256) sfc[i] = fc2_W[i];
    if (tid < NT) scb[tid] = crf_b[tid];
    if (tid < 2)  sfb[tid] = fc2_b[tid];
    __syncthreads();

    const int lane = tid & 31;
    const int gw   = (blockIdx.x * blockDim.x + tid) >> 5;
    const int nw   = (gridDim.x * blockDim.x) >> 5;

    for (int it = gw; it < 16384 + B; it += nw) {
        if (it < 16384) {
            const int b  = it >> 8;
            const int sp = it & 255;
            const size_t r0 = (size_t)b * S1 + 1 + 2 * sp;
            const float4* e0 = reinterpret_cast<const float4*>(emb + r0 * H);
            const float4* e1 = reinterpret_cast<const float4*>(emb + (r0 + 1) * H);
            float4 ev0[6], ev1[6];
#pragma unroll
            for (int k = 0; k < 6; k++) {
                ev0[k] = __ldcs(e0 + k * 32 + lane);
                ev1[k] = __ldcs(e1 + k * 32 + lane);
            }
            float a0[NT] = {0.f, 0.f, 0.f, 0.f};
            float a1[NT] = {0.f, 0.f, 0.f, 0.f};
#pragma unroll
            for (int k = 0; k < 6; k++) {
#pragma unroll
                for (int t = 0; t < NT; t++) {
                    float4 w = reinterpret_cast<const float4*>(sw + t * H)[k * 32 + lane];
                    a0[t] += ev0[k].x * w.x + ev0[k].y * w.y + ev0[k].z * w.z + ev0[k].w * w.w;
                    a1[t] += ev1[k].x * w.x + ev1[k].y * w.y + ev1[k].z * w.z + ev1[k].w * w.w;
                }
            }
#pragma unroll
            for (int off = 16; off; off >>= 1)
#pragma unroll
                for (int t = 0; t < NT; t++) {
                    a0[t] += __shfl_xor_sync(0xFFFFFFFFu, a0[t], off);
                    a1[t] += __shfl_xor_sync(0xFFFFFFFFu, a1[t], off);
                }
            if (lane == 0) {
                float4* dst = reinterpret_cast<float4*>(g_feats) + (b * S + 2 * sp);
                dst[0] = make_float4(a0[0] + scb[0], a0[1] + scb[1],
                                     a0[2] + scb[2], a0[3] + scb[3]);
                dst[1] = make_float4(a1[0] + scb[0], a1[1] + scb[1],
                                     a1[2] + scb[2], a1[3] + scb[3]);
            }
        } else {
            const int b = it - 16384;
            const float4* e = reinterpret_cast<const float4*>(emb + (size_t)b * S1 * H);
            float l0 = 0.f, l1 = 0.f;
#pragma unroll
            for (int k = 0; k < 6; k++) {
                float4 ev = __ldcs(e + k * 32 + lane);
                float4 w0 = reinterpret_cast<const float4*>(sfc)[k * 32 + lane];
                float4 w1 = reinterpret_cast<const float4*>(sfc + H)[k * 32 + lane];
                l0 += ev.x * w0.x + ev.y * w0.y + ev.z * w0.z + ev.w * w0.w;
                l1 += ev.x * w1.x + ev.y * w1.y + ev.z * w1.z + ev.w * w1.w;
            }
#pragma unroll
            for (int off = 16; off; off >>= 1) {
                l0 += __shfl_xor_sync(0xFFFFFFFFu, l0, off);
                l1 += __shfl_xor_sync(0xFFFFFFFFu, l1, off);
            }
            if (lane == 0) {
                g_logits[b * 2 + 0] = l0 + sfb[0];
                g_logits[b * 2 + 1] = l1 + sfb[1];
            }
        }
    }
}

// ---------------------------------------------------------------------------
// Kernel 2: per-batch CRF, SoA operator storage (conflict-free LDS).
//  Forward Z : binary tree over 255 M2 matrices (normalized + log accum)
//  Viterbi   : Hillis-Steele max-plus scan over 127 V4 ops, parallel
//              backtrace records, 127-step serial record chase.
// 256 threads/block, matrices stored [element][operator].
// ---------------------------------------------------------------------------
__global__ void __launch_bounds__(256) k_crf(const int* __restrict__ labels,
                                             const int* __restrict__ isqa,
                                             const float* __restrict__ trans,
                                             float* __restrict__ out) {
    __shared__ __align__(16) float sf[S * NT];     // 8 KB feats (log)
    __shared__ float sA[16 * PSTR];                // 16 KB: M2 then V2 (SoA)
    __shared__ float sV4[16 * QSTR];               // 8 KB (SoA)
    __shared__ float sPa[16 * QSTR];               // 8 KB tree/scan buffer (SoA)
    __shared__ float slogs[QSTR];
    __shared__ float strn[16], sE[16];
    __shared__ int   sbpmid2[PSTR];
    __shared__ int   skmid4[QSTR];
    __shared__ unsigned int srec[QSTR];
    __shared__ unsigned char stag[S], spath[S];
    __shared__ float sZ;

    const int b   = blockIdx.x;
    const int tid = threadIdx.x;
    const float4* sf4 = reinterpret_cast<const float4*>(sf);

    // ---- P0: stage ----
    {
        const float4* fsrc = reinterpret_cast<const float4*>(g_feats + (size_t)b * S * NT);
        float4* f4 = reinterpret_cast<float4*>(sf);
        for (int i = tid; i < S; i += 256) f4[i] = fsrc[i];
        for (int i = tid; i < S; i += 256) {
            int tg = labels[b * S1 + 1 + i];
            stag[i] = (unsigned char)tg;
            out[OFF_TAGS + b * S + i] = (float)tg;
        }
        if (tid < 16) { float t = trans[tid]; strn[tid] = t; sE[tid] = __expf(t); }
    }
    __syncthreads();

    // ---- P1: M2 pair matrices (linear domain), one per thread, SoA store ----
    if (tid < NP) {
        const int p = tid;
        float4 f1 = sf4[2 * p + 1], f2 = sf4[2 * p + 2];
        float g[4] = {__expf(f1.x), __expf(f1.y), __expf(f1.z), __expf(f1.w)};
        float h[4] = {__expf(f2.x), __expf(f2.y), __expf(f2.z), __expf(f2.w)};
        float m[16];
#pragma unroll
        for (int i = 0; i < 4; i++) {
            float eg0 = sE[i * 4 + 0] * g[0], eg1 = sE[i * 4 + 1] * g[1];
            float eg2 = sE[i * 4 + 2] * g[2], eg3 = sE[i * 4 + 3] * g[3];
#pragma unroll
            for (int j = 0; j < 4; j++)
                m[i * 4 + j] = ((eg0 * sE[0 * 4 + j] + eg1 * sE[1 * 4 + j]) +
                                (eg2 * sE[2 * 4 + j] + eg3 * sE[3 * 4 + j])) * h[j];
        }
#pragma unroll
        for (int e = 0; e < 16; e++) sA[e * PSTR + p] = m[e];
    }
    __syncthreads();

    // ---- P2: forward Z via tree reduction over sPa (SoA) ----
    if (tid < 128) {
        float C[16];
        if (tid < 127) {
            float A[16], Bm[16];
#pragma unroll
            for (int e = 0; e < 16; e++) { A[e] = sA[e * PSTR + 2 * tid];
                                           Bm[e] = sA[e * PSTR + 2 * tid + 1]; }
            mm4(A, Bm, C);
        } else {
#pragma unroll
            for (int e = 0; e < 16; e++) C[e] = sA[e * PSTR + 254];
        }
        float ssum = 0.f;
#pragma unroll
        for (int e = 0; e < 16; e++) ssum += C[e];
        float inv = __fdividef(1.0f, ssum);
#pragma unroll
        for (int e = 0; e < 16; e++) sPa[e * QSTR + tid] = C[e] * inv;
        slogs[tid] = __logf(ssum);
    }
    __syncthreads();
#pragma unroll
    for (int n = 64; n >= 1; n >>= 1) {
        float C[16], lg = 0.f;
        if (tid < n) {
            float A[16], Bm[16];
#pragma unroll
            for (int e = 0; e < 16; e++) { A[e] = sPa[e * QSTR + 2 * tid];
                                           Bm[e] = sPa[e * QSTR + 2 * tid + 1]; }
            mm4(A, Bm, C);
            lg = slogs[2 * tid] + slogs[2 * tid + 1];
        }
        __syncthreads();
        if (tid < n) {
            float ssum = 0.f;
#pragma unroll
            for (int e = 0; e < 16; e++) ssum += C[e];
            float inv = __fdividef(1.0f, ssum);
#pragma unroll
            for (int e = 0; e < 16; e++) sPa[e * QSTR + tid] = C[e] * inv;
            slogs[tid] = lg + __logf(ssum);
        }
        __syncthreads();
    }
    if (tid == 0) {   // Z epilogue: alpha0 . Mtot, then step 511 + stop
        float4 f0 = sf4[0];
        float a[4] = {__expf(f0.x) * sE[8],  __expf(f0.y) * sE[9],
                      __expf(f0.z) * sE[10], __expf(f0.w) * sE[11]};
        float Mt[16];
#pragma unroll
        for (int e = 0; e < 16; e++) Mt[e] = sPa[e * QSTR + 0];
        float t[4];
#pragma unroll
        for (int j = 0; j < 4; j++)
            t[j] = (a[0] * Mt[0 * 4 + j] + a[1] * Mt[1 * 4 + j]) +
                   (a[2] * Mt[2 * 4 + j] + a[3] * Mt[3 * 4 + j]);
        float4 f511 = sf4[511];
        float ef[4] = {__expf(f511.x), __expf(f511.y), __expf(f511.z), __expf(f511.w)};
        float u[4];
#pragma unroll
        for (int j = 0; j < 4; j++)
            u[j] = ((t[0] * sE[0 * 4 + j] + t[1] * sE[1 * 4 + j]) +
                    (t[2] * sE[2 * 4 + j] + t[3] * sE[3 * 4 + j])) * ef[j];
        sZ = slogs[0] + __logf((u[0] * sE[3] + u[1] * sE[7]) +
                               (u[2] * sE[11] + u[3] * sE[15]));
    }
    __syncthreads();

    // ---- P3: V2 (max-plus) overwrites sA (SoA); mid-tag words ----
    if (tid < NP) {
        const int p = tid;
        float4 f1 = sf4[2 * p + 1], f2 = sf4[2 * p + 2];
        float f1a[4] = {f1.x, f1.y, f1.z, f1.w};
        float f2a[4] = {f2.x, f2.y, f2.z, f2.w};
        int word = 0;
#pragma unroll
        for (int i = 0; i < 4; i++) {
            float h0 = strn[i * 4 + 0] + f1a[0], h1 = strn[i * 4 + 1] + f1a[1];
            float h2 = strn[i * 4 + 2] + f1a[2], h3 = strn[i * 4 + 3] + f1a[3];
#pragma unroll
            for (int j = 0; j < 4; j++) {
                float mv;
                int k = argmax4(h0 + strn[0 * 4 + j], h1 + strn[1 * 4 + j],
                                h2 + strn[2 * 4 + j], h3 + strn[3 * 4 + j], mv);
                sA[(i * 4 + j) * PSTR + p] = mv + f2a[j];
                word |= k << (2 * (i * 4 + j));
            }
        }
        sbpmid2[p] = word;
    }
    __syncthreads();

    // ---- P4: V4 = V2 o V2 into sV4 and sPa (scan init); mid words ----
    if (tid < NQ) {
        float A[16], Bv[16];
#pragma unroll
        for (int e = 0; e < 16; e++) { A[e] = sA[e * PSTR + 2 * tid];
                                       Bv[e] = sA[e * PSTR + 2 * tid + 1]; }
        int word = 0;
#pragma unroll
        for (int i = 0; i < 4; i++)
#pragma unroll
            for (int j = 0; j < 4; j++) {
                float mv;
                int k = argmax4(A[i * 4 + 0] + Bv[0 * 4 + j], A[i * 4 + 1] + Bv[1 * 4 + j],
                                A[i * 4 + 2] + Bv[2 * 4 + j], A[i * 4 + 3] + Bv[3 * 4 + j], mv);
                sV4[(i * 4 + j) * QSTR + tid] = mv;
                sPa[(i * 4 + j) * QSTR + tid] = mv;
                word |= k << (2 * (i * 4 + j));
            }
        skmid4[tid] = word;
    }
    __syncthreads();

    // ---- P5: inclusive max-plus scan (Hillis-Steele, SoA) ----
#pragma unroll
    for (int d = 1; d < 128; d <<= 1) {
        float C[16];
        const bool act = (tid < NQ) && (tid >= d);
        if (act) {
            float A[16], Bm[16];
#pragma unroll
            for (int e = 0; e < 16; e++) { A[e] = sPa[e * QSTR + tid - d];
                                           Bm[e] = sPa[e * QSTR + tid]; }
            mp4(A, Bm, C);
        }
        __syncthreads();
        if (act) {
#pragma unroll
            for (int e = 0; e < 16; e++) sPa[e * QSTR + tid] = C[e];
        }
        __syncthreads();
    }

    // ---- P6: per-quad backtrace records (parallel) ----
    if (tid < NQ) {
        const int q = tid;
        float4 f0 = sf4[0];
        float d0v[4] = {f0.x + strn[8], f0.y + strn[9], f0.z + strn[10], f0.w + strn[11]};
        float de[4];
        if (q == 0) {
#pragma unroll
            for (int i = 0; i < 4; i++) de[i] = d0v[i];
        } else {
            float P[16];
#pragma unroll
            for (int e = 0; e < 16; e++) P[e] = sPa[e * QSTR + q - 1];
#pragma unroll
            for (int j = 0; j < 4; j++) {
                float mv;
                argmax4(d0v[0] + P[0 * 4 + j], d0v[1] + P[1 * 4 + j],
                        d0v[2] + P[2 * 4 + j], d0v[3] + P[3 * 4 + j], mv);
                de[j] = mv;
            }
        }
        float V[16];
#pragma unroll
        for (int e = 0; e < 16; e++) V[e] = sV4[e * QSTR + q];
        const int w4 = skmid4[q], w2a = sbpmid2[2 * q], w2b = sbpmid2[2 * q + 1];
        unsigned int rec = 0;
#pragma unroll
        for (int j = 0; j < 4; j++) {
            float mv;
            int i = argmax4(de[0] + V[0 * 4 + j], de[1] + V[1 * 4 + j],
                            de[2] + V[2 * 4 + j], de[3] + V[3 * 4 + j], mv);
            int k2 = (w4  >> (2 * ((i  << 2) | j)))  & 3;
            int m1 = (w2a >> (2 * ((i  << 2) | k2))) & 3;
            int m3 = (w2b >> (2 * ((k2 << 2) | j)))  & 3;
            rec |= (unsigned int)(i | (m1 << 2) | (k2 << 4) | (m3 << 6)) << (8 * j);
        }
        srec[q] = rec;
    }
    __syncthreads();

    // ---- P7: viterbi epilogue + serial record chase (tid 0) ----
    if (tid == 0) {
        float4 f0 = sf4[0];
        float d0v[4] = {f0.x + strn[8], f0.y + strn[9], f0.z + strn[10], f0.w + strn[11]};
        float P[16];
#pragma unroll
        for (int e = 0; e < 16; e++) P[e] = sPa[e * QSTR + 126];
        float e[4];
#pragma unroll
        for (int j = 0; j < 4; j++) {
            float mv;
            argmax4(d0v[0] + P[0 * 4 + j], d0v[1] + P[1 * 4 + j],
                    d0v[2] + P[2 * 4 + j], d0v[3] + P[3 * 4 + j], mv);
            e[j] = mv;
        }
        float Vl[16];
#pragma unroll
        for (int k = 0; k < 16; k++) Vl[k] = sA[k * PSTR + 254];
        float g0 = fmaxf(fmaxf(e[0] + Vl[0], e[1] + Vl[4]), fmaxf(e[2] + Vl[8],  e[3] + Vl[12]));
        float g1 = fmaxf(fmaxf(e[0] + Vl[1], e[1] + Vl[5]), fmaxf(e[2] + Vl[9],  e[3] + Vl[13]));
        float g2 = fmaxf(fmaxf(e[0] + Vl[2], e[1] + Vl[6]), fmaxf(e[2] + Vl[10], e[3] + Vl[14]));
        float g3 = fmaxf(fmaxf(e[0] + Vl[3], e[1] + Vl[7]), fmaxf(e[2] + Vl[11], e[3] + Vl[15]));
        float4 f511 = sf4[511];
        float h0 = fmaxf(fmaxf(g0 + strn[0], g1 + strn[4]), fmaxf(g2 + strn[8],  g3 + strn[12])) + f511.x;
        float h1 = fmaxf(fmaxf(g0 + strn[1], g1 + strn[5]), fmaxf(g2 + strn[9],  g3 + strn[13])) + f511.y;
        float h2 = fmaxf(fmaxf(g0 + strn[2], g1 + strn[6]), fmaxf(g2 + strn[10], g3 + strn[14])) + f511.z;
        float h3 = fmaxf(fmaxf(g0 + strn[3], g1 + strn[7]), fmaxf(g2 + strn[11], g3 + strn[15])) + f511.w;
        float mv;
        int lt = argmax4(h0 + strn[3], h1 + strn[7], h2 + strn[11], h3 + strn[15], mv);
        spath[511] = (unsigned char)lt;
        int t510 = argmax4(g0 + strn[0 * 4 + lt], g1 + strn[1 * 4 + lt],
                           g2 + strn[2 * 4 + lt], g3 + strn[3 * 4 + lt], mv);
        spath[510] = (unsigned char)t510;
        int j = t510;
        int i508 = argmax4(e[0] + Vl[0 * 4 + j], e[1] + Vl[1 * 4 + j],
                           e[2] + Vl[2 * 4 + j], e[3] + Vl[3 * 4 + j], mv);
        int mid = (sbpmid2[254] >> (2 * ((i508 << 2) | j))) & 3;
        spath[509] = (unsigned char)mid;
        spath[508] = (unsigned char)i508;
        j = i508;
        unsigned int* path32 = reinterpret_cast<unsigned int*>(spath);
#pragma unroll 4
        for (int q = NQ - 1; q >= 0; q--) {
            unsigned int w = srec[q];
            unsigned int r = (w >> (8 * j)) & 255u;
            path32[q] = (r & 3u) | (((r >> 2) & 3u) << 8) |
                        (((r >> 4) & 3u) << 16) | (((r >> 6) & 3u) << 24);
            j = (int)(r & 3u);
        }
    }
    __syncthreads();

    // ---- P8: gold score (warp 0), isqa (tid 32), path writeback (all) ----
    const int warp = tid >> 5, lane = tid & 31;
    if (warp == 0) {
        float em = 0.f, tr = 0.f;
        for (int s = lane; s < S; s += 32)     em += sf[s * NT + stag[s]];
        for (int s = lane; s < S - 1; s += 32) tr += strn[stag[s] * NT + stag[s + 1]];
        float v = em + tr;
#pragma unroll
        for (int off = 16; off; off >>= 1) v += __shfl_xor_sync(0xFFFFFFFFu, v, off);
        if (lane == 0) {
            float gold = v + strn[8 + stag[0]] + strn[stag[S - 1] * 4 + 3];
            g_dloss[b] = sZ - gold;
        }
    } else if (tid == 32) {
        float l0 = g_logits[b * 2], l1 = g_logits[b * 2 + 1];
        float mm  = fmaxf(l0, l1);
        float lse = mm + __logf(__expf(l0 - mm) + __expf(l1 - mm));
        int y = isqa[b];
        g_iloss[b] = -((y ? l1 : l0) - lse);
        out[OFF_IPRED + b] = (l1 > l0) ? 1.0f : 0.0f;
        out[OFF_ISQA + b] = (float)y;
    }
    for (int i = tid; i < S; i += 256)
        out[OFF_CPRED + b * S + i] = (float)spath[i];
}

// ---------------------------------------------------------------------------
// Kernel 3: reduce per-batch losses
// ---------------------------------------------------------------------------
__global__ void k_final(float* __restrict__ out) {
    const int tid = threadIdx.x;   // 64 threads
    float d  = g_dloss[tid];
    float il = g_iloss[tid];
#pragma unroll
    for (int off = 16; off; off >>= 1) {
        d  += __shfl_xor_sync(0xFFFFFFFFu, d, off);
        il += __shfl_xor_sync(0xFFFFFFFFu, il, off);
    }
    __shared__ float sd2[2], si2[2];
    if ((tid & 31) == 0) { sd2[tid >> 5] = d; si2[tid >> 5] = il; }
    __syncthreads();
    if (tid == 0) {
        out[OFF_CLOSS] = (sd2[0] + sd2[1]) * (1.0f / 64.0f);
        out[OFF_ILOSS] = (si2[0] + si2[1]) * (1.0f / 64.0f);
    }
}

// ---------------------------------------------------------------------------
extern "C" void kernel_launch(void* const* d_in, const int* in_sizes, int n_in,
                              void* d_out, int out_size) {
    const float* emb    = (const float*)d_in[0];
    const int*   labels = (const int*)d_in[1];
    const int*   isqa   = (const int*)d_in[2];
    const float* fc2_W  = (const float*)d_in[3];
    const float* fc2_b  = (const float*)d_in[4];
    const float* crf_W  = (const float*)d_in[5];
    const float* crf_b  = (const float*)d_in[6];
    const float* trans  = (const float*)d_in[7];
    float* out = (float*)d_out;

    k_feats<<<444, 256>>>(emb, fc2_W, fc2_b, crf_W, crf_b);
    k_crf<<<B, 256>>>(labels, isqa, trans, out);
    k_final<<<1, 64>>>(out);
}